// round 1
// baseline (speedup 1.0000x reference)
#include <cuda_runtime.h>
#include <cuda_bf16.h>
#include <math.h>

// Problem constants
#define Bn 8
#define Tn 4096
#define Dn 64
#define Rn 64
#define STRENGTH 0.1f
#define PHI_SCALE 0.17677669529663687f  // sqrt(2/64)

// Scratch (device globals; no allocation allowed)
__device__ float g_phi[Bn * Tn * Rn];     // 8 MB
__device__ float g_phisum[Bn * Rn];       // 2 KB
__device__ float g_grav[Bn * Tn];         // 128 KB

// ---------------------------------------------------------------------------
// k0: zero phi_sum accumulator (needed every graph replay)
__global__ void k0_zero() {
    int i = blockIdx.x * blockDim.x + threadIdx.x;
    if (i < Bn * Rn) g_phisum[i] = 0.0f;
}

// ---------------------------------------------------------------------------
// k1: per-token mass + phi, accumulate mass-weighted phi_sum.
// grid = (CH=32, B), block = 256 (4 groups of 64 threads; 1 token per group
// per iteration; 128 tokens per block, 32 iterations).
#define CH 32
#define TOK_PER_BLK (Tn / CH)   // 128

__global__ __launch_bounds__(256) void k1_phi_mass(
    const float* __restrict__ coords,
    const float* __restrict__ w1, const float* __restrict__ b1,
    const float* __restrict__ w2, const float* __restrict__ b2,
    const float* __restrict__ W,  const float* __restrict__ b)
{
    __shared__ float w1s[Dn * (Dn + 1)];  // padded stride 65: kills bank conflicts
    __shared__ float Ws[Dn * Rn];
    __shared__ float b1s[Dn], w2s[Dn], bs[Rn];
    __shared__ float xs[4][Dn];
    __shared__ float wsum[8];
    __shared__ float ms[4];
    __shared__ float red[256];

    const int tid = threadIdx.x;
    const int g   = tid >> 6;     // group 0..3
    const int j   = tid & 63;     // lane-in-group = output index
    const int bi  = blockIdx.y;
    const int chunk = blockIdx.x;

    // Stage weights into smem
    for (int i = tid; i < Dn * Dn; i += 256) {
        w1s[(i >> 6) * (Dn + 1) + (i & 63)] = w1[i];
        Ws[i] = W[i];
    }
    if (tid < Dn) { b1s[tid] = b1[tid]; w2s[tid] = w2[tid]; bs[tid] = b[tid]; }
    __syncthreads();

    const float b2v = b2[0];
    float acc = 0.0f;  // local phi_sum accumulator for index j

    for (int it = 0; it < TOK_PER_BLK / 4; ++it) {
        const int t = chunk * TOK_PER_BLK + it * 4 + g;
        const long base = ((long)bi * Tn + t) * Dn;

        xs[g][j] = coords[base + j];
        __syncthreads();

        // mass-net hidden: h_j = relu(b1_j + sum_d x_d * w1[j][d])
        float h = b1s[j];
        #pragma unroll
        for (int d = 0; d < Dn; ++d) h = fmaf(xs[g][d], w1s[j * (Dn + 1) + d], h);
        h = fmaxf(h, 0.0f);

        // mass_pre = sum_j h_j * w2_j  (reduce over 64 threads = 2 warps)
        float c = h * w2s[j];
        #pragma unroll
        for (int o = 16; o > 0; o >>= 1) c += __shfl_xor_sync(0xFFFFFFFFu, c, o);
        if ((tid & 31) == 0) wsum[tid >> 5] = c;
        __syncthreads();
        if (j == 0) {
            float m = wsum[2 * g] + wsum[2 * g + 1] + b2v;
            // softplus = log1p(exp(m)), stable
            ms[g] = (m > 20.0f) ? m : log1pf(__expf(m));
        }
        __syncthreads();
        const float mass = ms[g];

        // RFF: phi_j = sqrt(2/R) * cos(sum_d x_d * W[d][j] + b_j)
        float dw = bs[j];
        #pragma unroll
        for (int d = 0; d < Dn; ++d) dw = fmaf(xs[g][d], Ws[d * Rn + j], dw);
        float phi = PHI_SCALE * cosf(dw);

        g_phi[base + j] = phi;          // base works since Dn == Rn
        acc = fmaf(mass, phi, acc);
        __syncthreads();
    }

    // Reduce the 4 groups' accumulators, one atomicAdd per r per block
    red[tid] = acc;
    __syncthreads();
    if (g == 0) {
        float s = red[j] + red[64 + j] + red[128 + j] + red[192 + j];
        atomicAdd(&g_phisum[bi * Rn + j], s);
    }
}

// ---------------------------------------------------------------------------
// k2: grav[b,t] = dot(phi[b,t,:], phi_sum[b,:]). One warp per token.
__global__ __launch_bounds__(256) void k2_grav() {
    const int warp = (blockIdx.x * blockDim.x + threadIdx.x) >> 5;
    const int lane = threadIdx.x & 31;
    if (warp >= Bn * Tn) return;
    const int bi = warp >> 12;  // Tn = 4096
    const float* phi = &g_phi[(long)warp * Rn];
    const float* ps  = &g_phisum[bi * Rn];
    float s = phi[lane] * ps[lane] + phi[lane + 32] * ps[lane + 32];
    #pragma unroll
    for (int o = 16; o > 0; o >>= 1) s += __shfl_xor_sync(0xFFFFFFFFu, s, o);
    if (lane == 0) g_grav[warp] = s;
}

// ---------------------------------------------------------------------------
// k3: out = G + 0.1*grav*I  — the 1 GB streaming pass.
// One block per (b,t) tile: 4096 floats = 1024 float4 = 256 threads x 4.
__global__ __launch_bounds__(256) void k3_copy(
    const float* __restrict__ G, float* __restrict__ out)
{
    const int tk = blockIdx.x;                   // token id in [0, B*T)
    const float gs = STRENGTH * g_grav[tk];
    const long base4 = (long)tk * 1024;          // float4 units
    const float4* __restrict__ Gp = (const float4*)G;
    float4* __restrict__ Op = (float4*)out;

    #pragma unroll
    for (int it = 0; it < 4; ++it) {
        const int k = threadIdx.x + it * 256;    // float4 index in tile [0,1024)
        float4 v = Gp[base4 + k];
        const int m = (4 * k) % 65;              // diag iff (4k + lane) % 65 == 0
        if      (m == 0)  v.x += gs;
        else if (m == 64) v.y += gs;
        else if (m == 63) v.z += gs;
        else if (m == 62) v.w += gs;
        Op[base4 + k] = v;
    }
}

// ---------------------------------------------------------------------------
extern "C" void kernel_launch(void* const* d_in, const int* in_sizes, int n_in,
                              void* d_out, int out_size) {
    const float* G      = (const float*)d_in[0];
    const float* coords = (const float*)d_in[1];
    const float* w1     = (const float*)d_in[2];
    const float* b1     = (const float*)d_in[3];
    const float* w2     = (const float*)d_in[4];
    const float* b2     = (const float*)d_in[5];
    const float* W      = (const float*)d_in[6];
    const float* b      = (const float*)d_in[7];
    float* out = (float*)d_out;

    k0_zero<<<1, 512>>>();
    k1_phi_mass<<<dim3(CH, Bn), 256>>>(coords, w1, b1, w2, b2, W, b);
    k2_grav<<<(Bn * Tn) / 8, 256>>>();
    k3_copy<<<Bn * Tn, 256>>>(G, out);
}

// round 3
// speedup vs baseline: 1.1320x; 1.1320x over previous
#include <cuda_runtime.h>
#include <cuda_bf16.h>
#include <math.h>

// Problem constants
#define Bn 8
#define Tn 4096
#define Dn 64
#define Rn 64
#define NTOK (Bn * Tn)            // 32768
#define STRENGTH 0.1f
#define PHI_SCALE 0.17677669529663687f  // sqrt(2/64)

// Scratch (device globals; no allocation allowed)
__device__ float g_phi[NTOK * Rn];        // 8 MB
__device__ float g_phisum[Bn * Rn];       // 2 KB
__device__ float g_grav[NTOK];            // 128 KB (unused now, kept for safety)

// ---------------------------------------------------------------------------
// k0: zero phi_sum accumulator (needed every graph replay)
__global__ void k0_zero() {
    int i = blockIdx.x * blockDim.x + threadIdx.x;
    if (i < Bn * Rn) g_phisum[i] = 0.0f;
}

// ---------------------------------------------------------------------------
// k1: per-token mass + phi with REGISTER-RESIDENT weights.
// Block = 256 threads = 4 teams of 64 (2 warps each). Thread j of a team
// holds w1 row j and W column j in registers; x broadcast from smem, each
// x-load shared by BOTH dot products (64 LDS + 128 FMA per token/thread).
// Flat grid of 148 blocks (1 per SM at ~170 regs) for perfect wave balance.
#define K1_BLOCKS 148

__global__ __launch_bounds__(256) void k1_phi_mass(
    const float* __restrict__ coords,
    const float* __restrict__ w1, const float* __restrict__ b1,
    const float* __restrict__ w2, const float* __restrict__ b2,
    const float* __restrict__ W,  const float* __restrict__ b)
{
    __shared__ float w1s[Dn * (Dn + 1)];  // one-time staging, stride 65 (conflict-free unpack)
    __shared__ float xs[4][Dn];           // per-team x buffer
    __shared__ float wsum[8];             // per-warp partial for mass reduce
    __shared__ float red[256];            // final phisum block reduce

    const int tid  = threadIdx.x;
    const int team = tid >> 6;     // 0..3
    const int j    = tid & 63;     // output index within team
    const int warp = tid >> 5;     // 0..7
    const int lane = tid & 31;
    const int barid = team + 1;    // named barrier per team (64 threads)

    // Flat token range for this block (32768 over 148 blocks: 221 or 222)
    const int t0   = (int)(((long)blockIdx.x * NTOK) / K1_BLOCKS);
    const int t1   = (int)(((long)(blockIdx.x + 1) * NTOK) / K1_BLOCKS);
    const int iters = (t1 - t0 + 3) >> 2;

    // Stage w1 coalesced into padded smem, then unpack rows into registers.
    for (int i = tid; i < Dn * Dn; i += 256)
        w1s[(i >> 6) * (Dn + 1) + (i & 63)] = w1[i];
    __syncthreads();

    float w1r[Dn], wtr[Dn];
    #pragma unroll
    for (int d = 0; d < Dn; ++d) w1r[d] = w1s[j * (Dn + 1) + d];  // conflict-free (j+d banks)
    #pragma unroll
    for (int d = 0; d < Dn; ++d) wtr[d] = W[d * Rn + j];          // coalesced across lanes

    const float b1j = b1[j];
    const float w2j = w2[j];
    const float bj  = b[j];
    const float b2v = b2[0];

    // per-j accumulators, one per batch contribution handled via direct index
    float acc = 0.0f;
    int   cur_b = t0 / Tn;   // batch of first token (flushed when batch changes)

    for (int it = 0; it < iters; ++it) {
        const int t = t0 + it * 4 + team;
        const bool valid = (t < t1);
        const int  tb = valid ? (t / Tn) : cur_b;
        const long base = (long)t * Dn;

        if (valid) xs[team][j] = coords[base + j];
        asm volatile("bar.sync %0, 64;" :: "r"(barid) : "memory");

        // Both dots share each x broadcast load.
        float h0 = b1j, h1 = 0.f, h2 = 0.f, h3 = 0.f;
        float a0 = bj,  a1 = 0.f, a2 = 0.f, a3 = 0.f;
        #pragma unroll
        for (int d = 0; d < Dn; d += 4) {
            const float x0 = xs[team][d + 0];
            const float x1 = xs[team][d + 1];
            const float x2 = xs[team][d + 2];
            const float x3 = xs[team][d + 3];
            h0 = fmaf(x0, w1r[d + 0], h0);  a0 = fmaf(x0, wtr[d + 0], a0);
            h1 = fmaf(x1, w1r[d + 1], h1);  a1 = fmaf(x1, wtr[d + 1], a1);
            h2 = fmaf(x2, w1r[d + 2], h2);  a2 = fmaf(x2, wtr[d + 2], a2);
            h3 = fmaf(x3, w1r[d + 3], h3);  a3 = fmaf(x3, wtr[d + 3], a3);
        }
        float h = fmaxf((h0 + h1) + (h2 + h3), 0.0f);
        float phi = PHI_SCALE * cosf((a0 + a1) + (a2 + a3));

        // mass_pre = sum_j h_j * w2_j  (2-warp reduce via smem, one barrier)
        float c = h * w2j;
        #pragma unroll
        for (int o = 16; o > 0; o >>= 1) c += __shfl_xor_sync(0xFFFFFFFFu, c, o);
        if (lane == 0) wsum[warp] = c;
        asm volatile("bar.sync %0, 64;" :: "r"(barid) : "memory");
        // every thread computes mass locally (cheaper than a 3rd barrier)
        const float m = wsum[2 * team] + wsum[2 * team + 1] + b2v;
        const float mass = (m > 20.0f) ? m : log1pf(__expf(m));

        if (valid) {
            // flush accumulator on batch boundary (ranges can straddle batches)
            if (tb != cur_b) {
                atomicAdd(&g_phisum[cur_b * Rn + j], acc);  // per-thread flush
                acc = 0.0f;
                cur_b = tb;
            }
            g_phi[base + j] = phi;          // base works since Dn == Rn
            acc = fmaf(mass, phi, acc);
        }
        // next iteration's x-store is safe: all xs reads happened before bar2
    }

    // NOTE: teams within a block may end on different batches; reduce only
    // teams that share cur_b via smem tagged reduce. Simplest correct path:
    // flush per-thread accumulator directly (64 atomics per team).
    atomicAdd(&g_phisum[cur_b * Rn + j], acc);
    (void)red; (void)wsum;
}

// ---------------------------------------------------------------------------
// k3: out = G + 0.1*grav*I with the grav dot FUSED (per-warp redundant,
// barrier-free). One block per (b,t) tile: 1024 float4 = 256 thr x 4.
__global__ __launch_bounds__(256) void k3_copy(
    const float* __restrict__ G, float* __restrict__ out)
{
    const int tk = blockIdx.x;                   // token id in [0, B*T)
    const int bi = tk >> 12;                     // batch (Tn = 4096)
    const int lane = threadIdx.x & 31;
    const long base4 = (long)tk * 1024;          // float4 units
    const float4* __restrict__ Gp = (const float4*)G;
    float4* __restrict__ Op = (float4*)out;

    // Issue the DRAM loads first so the L2 dot hides beneath them.
    float4 v[4];
    #pragma unroll
    for (int it = 0; it < 4; ++it)
        v[it] = __ldcs(&Gp[base4 + threadIdx.x + it * 256]);

    // grav = dot(phi[tk,:], phisum[bi,:]) — redundant per warp, no barrier.
    const float* __restrict__ phi = &g_phi[(long)tk * Rn];
    const float* __restrict__ ps  = &g_phisum[bi * Rn];
    float s = phi[lane] * ps[lane] + phi[lane + 32] * ps[lane + 32];
    #pragma unroll
    for (int o = 16; o > 0; o >>= 1) s += __shfl_xor_sync(0xFFFFFFFFu, s, o);
    const float gs = STRENGTH * s;

    #pragma unroll
    for (int it = 0; it < 4; ++it) {
        const int k = threadIdx.x + it * 256;    // float4 index in tile [0,1024)
        const int m = (4 * k) % 65;              // diag iff (4k + lane) % 65 == 0
        if      (m == 0)  v[it].x += gs;
        else if (m == 64) v[it].y += gs;
        else if (m == 63) v[it].z += gs;
        else if (m == 62) v[it].w += gs;
        __stcs(&Op[base4 + k], v[it]);
    }
}

// ---------------------------------------------------------------------------
extern "C" void kernel_launch(void* const* d_in, const int* in_sizes, int n_in,
                              void* d_out, int out_size) {
    const float* G      = (const float*)d_in[0];
    const float* coords = (const float*)d_in[1];
    const float* w1     = (const float*)d_in[2];
    const float* b1     = (const float*)d_in[3];
    const float* w2     = (const float*)d_in[4];
    const float* b2     = (const float*)d_in[5];
    const float* W      = (const float*)d_in[6];
    const float* b      = (const float*)d_in[7];
    float* out = (float*)d_out;

    k0_zero<<<1, 512>>>();
    k1_phi_mass<<<K1_BLOCKS, 256>>>(coords, w1, b1, w2, b2, W, b);
    k3_copy<<<NTOK, 256>>>(G, out);
}

// round 11
// speedup vs baseline: 1.2459x; 1.1007x over previous
#include <cuda_runtime.h>
#include <cuda_bf16.h>
#include <math.h>

// Problem constants
#define Bn 8
#define Tn 4096
#define Dn 64
#define Rn 64
#define NTOK (Bn * Tn)            // 32768
#define STRENGTH 0.1f
#define PHI_SCALE 0.17677669529663687f  // sqrt(2/64)

// Scratch (device globals; zero-initialized at load, restored to zero by the
// tail of k3 every call -> graph-replay safe, no zeroing launch needed)
__device__ float g_phi[NTOK * Rn];        // 8 MB
__device__ float g_phisum[Bn * Rn];       // 2 KB
__device__ unsigned int g_ctr;            // k3 completion counter

// ---- packed f32x2 helpers (FFMA2: 2 MACs per issue slot, PTX-only) --------
__device__ __forceinline__ void ffma2(unsigned long long& acc,
                                      unsigned long long x,
                                      unsigned long long w) {
    asm("fma.rn.f32x2 %0, %1, %2, %0;" : "+l"(acc) : "l"(x), "l"(w));
}
__device__ __forceinline__ unsigned long long pack2(float lo, float hi) {
    unsigned long long r;
    asm("mov.b64 %0, {%1, %2};" : "=l"(r) : "f"(lo), "f"(hi));
    return r;
}
__device__ __forceinline__ float2 unpack2(unsigned long long v) {
    float2 r;
    asm("mov.b64 {%0, %1}, %2;" : "=f"(r.x), "=f"(r.y) : "l"(v));
    return r;
}

// ---------------------------------------------------------------------------
// k1: per-token mass + phi. Register-resident PACKED weights + FFMA2.
// Block = 256 = 4 teams of 64 (2 warps each). Thread j of a team holds
// w1 row j and W column j as 32 packed f32x2 pairs each; x is broadcast via
// smem and read as packed 64-bit pairs. 64 FFMA2 per token per thread.
#define K1_BLOCKS 148

__global__ __launch_bounds__(256) void k1_phi_mass(
    const float* __restrict__ coords,
    const float* __restrict__ w1, const float* __restrict__ b1,
    const float* __restrict__ w2, const float* __restrict__ b2,
    const float* __restrict__ W,  const float* __restrict__ b)
{
    __shared__ float w1s[Dn * (Dn + 1)];            // one-time staging, stride 65
    __shared__ __align__(16) float xs[4][Dn];       // per-team x buffer; 16B-aligned
    __shared__ float wsum[8];                       // per-warp partial for mass reduce

    const int tid  = threadIdx.x;
    const int team = tid >> 6;     // 0..3
    const int j    = tid & 63;     // output index within team
    const int warp = tid >> 5;     // 0..7
    const int lane = tid & 31;
    const int barid = team + 1;    // named barrier per team (64 threads)

    // Flat token range for this block (221 or 222 tokens)
    const int t0 = (int)(((long)blockIdx.x * NTOK) / K1_BLOCKS);
    const int t1 = (int)(((long)(blockIdx.x + 1) * NTOK) / K1_BLOCKS);
    const int iters = (t1 - t0 + 3) >> 2;

    // Stage w1 coalesced into padded smem (conflict-free unpack at stride 65).
    for (int i = tid; i < Dn * Dn; i += 256)
        w1s[(i >> 6) * (Dn + 1) + (i & 63)] = w1[i];
    __syncthreads();

    // Packed weights: wph[i] = {w1[j][2i], w1[j][2i+1]}, wpa[i] = {W[2i][j], W[2i+1][j]}
    unsigned long long wph[Dn / 2], wpa[Dn / 2];
    #pragma unroll
    for (int i = 0; i < Dn / 2; ++i)
        wph[i] = pack2(w1s[j * (Dn + 1) + 2 * i], w1s[j * (Dn + 1) + 2 * i + 1]);
    #pragma unroll
    for (int i = 0; i < Dn / 2; ++i)
        wpa[i] = pack2(W[(2 * i) * Rn + j], W[(2 * i + 1) * Rn + j]);  // coalesced

    const float b1j = b1[j];
    const float w2j = w2[j];
    const float bj  = b[j];
    const float b2v = b2[0];

    float acc = 0.0f;
    int   cur_b = t0 / Tn;

    // Prefetch first token's coord into the team buffer.
    {
        const int tc = t0 + team;
        xs[team][j] = (tc < t1) ? coords[(long)tc * Dn + j] : 0.0f;
    }

    const unsigned long long* __restrict__ xs8 =
        (const unsigned long long*)&xs[team][0];    // 256B team stride: 16B aligned

    for (int it = 0; it < iters; ++it) {
        const int t = t0 + it * 4 + team;
        const bool valid = (t < t1);
        const int  tb = valid ? (t / Tn) : cur_b;
        const long base = (long)t * Dn;

        asm volatile("bar.sync %0, 64;" :: "r"(barid) : "memory");

        // Prefetch next iteration's coord into a register (hidden under dots)
        const int tn = t + 4;
        float xnext = 0.0f;
        if (tn < t1) xnext = coords[(long)tn * Dn + j];

        // Packed dual-dot: 64 FFMA2 total, 2-way packed-accumulator ILP each.
        unsigned long long h0 = pack2(b1j, 0.0f), h1 = pack2(0.0f, 0.0f);
        unsigned long long a0 = pack2(bj, 0.0f),  a1 = pack2(0.0f, 0.0f);
        #pragma unroll
        for (int i = 0; i < Dn / 2; i += 2) {
            const unsigned long long x0 = xs8[i];
            const unsigned long long x1 = xs8[i + 1];
            ffma2(h0, x0, wph[i]);      ffma2(a0, x0, wpa[i]);
            ffma2(h1, x1, wph[i + 1]);  ffma2(a1, x1, wpa[i + 1]);
        }
        const float2 hu0 = unpack2(h0), hu1 = unpack2(h1);
        const float2 au0 = unpack2(a0), au1 = unpack2(a1);
        const float h   = fmaxf((hu0.x + hu0.y) + (hu1.x + hu1.y), 0.0f);
        const float phi = PHI_SCALE * __cosf((au0.x + au0.y) + (au1.x + au1.y));

        // mass_pre = sum_j h_j * w2_j  (2-warp reduce, one barrier)
        float c = h * w2j;
        #pragma unroll
        for (int o = 16; o > 0; o >>= 1) c += __shfl_xor_sync(0xFFFFFFFFu, c, o);
        if (lane == 0) wsum[warp] = c;
        asm volatile("bar.sync %0, 64;" :: "r"(barid) : "memory");

        // Publish next x only after all reads of current xs are done (bar above);
        // next iteration's leading barrier orders this store before its reads.
        xs[team][j] = xnext;

        // Fast stable softplus, computed redundantly by all 64 threads.
        const float m = wsum[2 * team] + wsum[2 * team + 1] + b2v;
        const float mass = (m > 15.0f) ? m : __logf(1.0f + __expf(m));

        if (valid) {
            if (tb != cur_b) {                       // batch-boundary flush
                atomicAdd(&g_phisum[cur_b * Rn + j], acc);
                acc = 0.0f;
                cur_b = tb;
            }
            g_phi[base + j] = phi;                   // Dn == Rn
            acc = fmaf(mass, phi, acc);
        }
    }

    atomicAdd(&g_phisum[cur_b * Rn + j], acc);
}

// ---------------------------------------------------------------------------
// k3: out = G + 0.1*grav*I, grav dot done ONCE per block (warp 0 -> smem) to
// keep L2 side-traffic negligible. G loads issued before the barrier so they
// stay in flight. Tail: last block resets phisum + counter for next replay.
__global__ __launch_bounds__(256) void k3_copy(
    const float* __restrict__ G, float* __restrict__ out)
{
    __shared__ float gs_sh;
    const int tk = blockIdx.x;                   // token id in [0, B*T)
    const int bi = tk >> 12;                     // batch (Tn = 4096)
    const int lane = threadIdx.x & 31;
    const long base4 = (long)tk * 1024;          // float4 units
    const float4* __restrict__ Gp = (const float4*)G;
    float4* __restrict__ Op = (float4*)out;

    // Issue the DRAM loads first; they remain in flight across the barrier.
    float4 v[4];
    #pragma unroll
    for (int it = 0; it < 4; ++it)
        v[it] = __ldcs(&Gp[base4 + threadIdx.x + it * 256]);

    // Warp 0 computes grav = dot(phi[tk,:], phisum[bi,:]) once.
    if (threadIdx.x < 32) {
        const float* __restrict__ phi = &g_phi[(long)tk * Rn];
        const float* __restrict__ ps  = &g_phisum[bi * Rn];
        float s = phi[lane] * ps[lane] + phi[lane + 32] * ps[lane + 32];
        #pragma unroll
        for (int o = 16; o > 0; o >>= 1) s += __shfl_xor_sync(0xFFFFFFFFu, s, o);
        if (lane == 0) gs_sh = STRENGTH * s;
    }
    __syncthreads();
    const float gs = gs_sh;

    #pragma unroll
    for (int it = 0; it < 4; ++it) {
        const int k = threadIdx.x + it * 256;    // float4 index in tile
        const int m = (4 * k) % 65;              // diag iff (4k + comp) % 65 == 0
        if      (m == 0)  v[it].x += gs;
        else if (m == 64) v[it].y += gs;
        else if (m == 63) v[it].z += gs;
        else if (m == 62) v[it].w += gs;
        __stcs(&Op[base4 + k], v[it]);
    }

    // Replay-state reset: last block to finish zeroes phisum and the counter.
    if (threadIdx.x == 0) {
        __threadfence();
        const unsigned int done = atomicAdd(&g_ctr, 1u);
        if (done == (unsigned int)(NTOK - 1)) {
            for (int i = 0; i < Bn * Rn; ++i) g_phisum[i] = 0.0f;
            g_ctr = 0u;
        }
    }
}

// ---------------------------------------------------------------------------
extern "C" void kernel_launch(void* const* d_in, const int* in_sizes, int n_in,
                              void* d_out, int out_size) {
    const float* G      = (const float*)d_in[0];
    const float* coords = (const float*)d_in[1];
    const float* w1     = (const float*)d_in[2];
    const float* b1     = (const float*)d_in[3];
    const float* w2     = (const float*)d_in[4];
    const float* b2     = (const float*)d_in[5];
    const float* W      = (const float*)d_in[6];
    const float* b      = (const float*)d_in[7];
    float* out = (float*)d_out;

    k1_phi_mass<<<K1_BLOCKS, 256>>>(coords, w1, b1, w2, b2, W, b);
    k3_copy<<<NTOK, 256>>>(G, out);
}

// round 12
// speedup vs baseline: 1.2602x; 1.0114x over previous
#include <cuda_runtime.h>
#include <cuda_bf16.h>
#include <math.h>

// Problem constants
#define Bn 8
#define Tn 4096
#define Dn 64
#define Rn 64
#define NTOK (Bn * Tn)            // 32768
#define STRENGTH 0.1f
#define PHI_SCALE 0.17677669529663687f  // sqrt(2/64)

// Scratch (device globals; zero-initialized at load, restored to zero by the
// tail of k3 every call -> graph-replay safe, no zeroing launch needed)
__device__ float g_phi[NTOK * Rn];        // 8 MB
__device__ float g_phisum[Bn * Rn];       // 2 KB
__device__ unsigned int g_ctr;            // k3 completion counter

// ---- packed f32x2 helpers (FFMA2: 2 MACs per issue slot, PTX-only) --------
__device__ __forceinline__ void ffma2(unsigned long long& acc,
                                      unsigned long long x,
                                      unsigned long long w) {
    asm("fma.rn.f32x2 %0, %1, %2, %0;" : "+l"(acc) : "l"(x), "l"(w));
}
__device__ __forceinline__ unsigned long long pack2(float lo, float hi) {
    unsigned long long r;
    asm("mov.b64 %0, {%1, %2};" : "=l"(r) : "f"(lo), "f"(hi));
    return r;
}
__device__ __forceinline__ float2 unpack2(unsigned long long v) {
    float2 r;
    asm("mov.b64 {%0, %1}, %2;" : "=f"(r.x), "=f"(r.y) : "l"(v));
    return r;
}

// ---------------------------------------------------------------------------
// k1: per-token mass + phi. Register-resident PACKED weights + FFMA2, with
// 4-token batching per team per barrier round to amortize barrier/shuffle/
// softplus overhead (the dominant cost at 1 token/round).
// Block = 256 = 4 teams of 64 (2 warps each); 16 tokens per block-iteration.
#define K1_BLOCKS 148
#define TPT 4                     // tokens per team per iteration
#define TPI (4 * TPT)             // tokens per block-iteration = 16

__global__ __launch_bounds__(256) void k1_phi_mass(
    const float* __restrict__ coords,
    const float* __restrict__ w1, const float* __restrict__ b1,
    const float* __restrict__ w2, const float* __restrict__ b2,
    const float* __restrict__ W,  const float* __restrict__ b)
{
    __shared__ float w1s[Dn * (Dn + 1)];            // one-time staging, stride 65
    __shared__ __align__(16) float xs[4][TPT][Dn];  // (team, slot, d); 16B-aligned
    __shared__ float wsum[8][TPT];                  // per-warp partials per slot

    const int tid  = threadIdx.x;
    const int team = tid >> 6;     // 0..3
    const int j    = tid & 63;     // output index within team
    const int warp = tid >> 5;     // 0..7
    const int lane = tid & 31;
    const int barid = team + 1;    // named barrier per team (64 threads)

    // Flat token range for this block (221 or 222 tokens)
    const int t0 = (int)(((long)blockIdx.x * NTOK) / K1_BLOCKS);
    const int t1 = (int)(((long)(blockIdx.x + 1) * NTOK) / K1_BLOCKS);
    const int iters = (t1 - t0 + TPI - 1) / TPI;

    // Stage w1 coalesced into padded smem (conflict-free unpack at stride 65).
    for (int i = tid; i < Dn * Dn; i += 256)
        w1s[(i >> 6) * (Dn + 1) + (i & 63)] = w1[i];
    __syncthreads();

    // Packed weights: wph[i] = {w1[j][2i], w1[j][2i+1]}, wpa[i] = {W[2i][j], W[2i+1][j]}
    unsigned long long wph[Dn / 2], wpa[Dn / 2];
    #pragma unroll
    for (int i = 0; i < Dn / 2; ++i)
        wph[i] = pack2(w1s[j * (Dn + 1) + 2 * i], w1s[j * (Dn + 1) + 2 * i + 1]);
    #pragma unroll
    for (int i = 0; i < Dn / 2; ++i)
        wpa[i] = pack2(W[(2 * i) * Rn + j], W[(2 * i + 1) * Rn + j]);  // coalesced

    const float b1j = b1[j];
    const float w2j = w2[j];
    const float bj  = b[j];
    const float b2v = b2[0];

    float acc = 0.0f;
    int   cur_b = t0 / Tn;
    int   nextb = (cur_b + 1) * Tn;   // first token of the next batch

    // Prefetch first 4 tokens' coords into the team buffer.
    #pragma unroll
    for (int s = 0; s < TPT; ++s) {
        const int tc = t0 + team * TPT + s;
        xs[team][s][j] = (tc < t1) ? coords[(long)tc * Dn + j] : 0.0f;
    }

    for (int it = 0; it < iters; ++it) {
        const int tbase = t0 + it * TPI + team * TPT;   // this team's 4 tokens

        asm volatile("bar.sync %0, 64;" :: "r"(barid) : "memory");

        // Prefetch next iteration's 4 coords into registers (hidden under dots)
        float xn[TPT];
        #pragma unroll
        for (int s = 0; s < TPT; ++s) {
            const int tn = tbase + TPI + s;
            xn[s] = (tn < t1) ? coords[(long)tn * Dn + j] : 0.0f;
        }

        // 4 packed dual-dots: 64 FFMA2 + 16 LDS.128 per token per thread.
        float h[TPT], phi[TPT];
        #pragma unroll
        for (int s = 0; s < TPT; ++s) {
            const ulonglong2* __restrict__ xp =
                (const ulonglong2*)&xs[team][s][0];     // 16B-aligned
            unsigned long long h0 = pack2(b1j, 0.0f), h1 = pack2(0.0f, 0.0f);
            unsigned long long a0 = pack2(bj, 0.0f),  a1 = pack2(0.0f, 0.0f);
            #pragma unroll
            for (int i = 0; i < Dn / 4; ++i) {
                const ulonglong2 x2 = xp[i];            // pairs {4i,4i+1},{4i+2,4i+3}
                ffma2(h0, x2.x, wph[2 * i]);      ffma2(a0, x2.x, wpa[2 * i]);
                ffma2(h1, x2.y, wph[2 * i + 1]);  ffma2(a1, x2.y, wpa[2 * i + 1]);
            }
            const float2 hu0 = unpack2(h0), hu1 = unpack2(h1);
            const float2 au0 = unpack2(a0), au1 = unpack2(a1);
            h[s]   = fmaxf((hu0.x + hu0.y) + (hu1.x + hu1.y), 0.0f);
            phi[s] = PHI_SCALE * __cosf((au0.x + au0.y) + (au1.x + au1.y));
        }

        // 4 interleaved 2-warp reduces (chains pipeline: ~latency of one)
        float c[TPT];
        #pragma unroll
        for (int s = 0; s < TPT; ++s) c[s] = h[s] * w2j;
        #pragma unroll
        for (int o = 16; o > 0; o >>= 1) {
            #pragma unroll
            for (int s = 0; s < TPT; ++s)
                c[s] += __shfl_xor_sync(0xFFFFFFFFu, c[s], o);
        }
        if (lane == 0) {
            #pragma unroll
            for (int s = 0; s < TPT; ++s) wsum[warp][s] = c[s];
        }
        asm volatile("bar.sync %0, 64;" :: "r"(barid) : "memory");

        // Publish next 4 x-vectors (all reads of current xs completed above).
        #pragma unroll
        for (int s = 0; s < TPT; ++s) xs[team][s][j] = xn[s];

        // Per-token mass (fast stable softplus, redundant across 64 threads),
        // phi store and mass-weighted accumulation with batch-boundary flush.
        #pragma unroll
        for (int s = 0; s < TPT; ++s) {
            const int t = tbase + s;
            if (t < t1) {
                const float m = wsum[2 * team][s] + wsum[2 * team + 1][s] + b2v;
                const float mass = (m > 15.0f) ? m : __logf(1.0f + __expf(m));
                if (t >= nextb) {                     // crossed into next batch
                    atomicAdd(&g_phisum[cur_b * Rn + j], acc);
                    acc = 0.0f;
                    ++cur_b;
                    nextb += Tn;
                }
                g_phi[(long)t * Dn + j] = phi[s];     // Dn == Rn
                acc = fmaf(mass, phi[s], acc);
            }
        }
    }

    atomicAdd(&g_phisum[cur_b * Rn + j], acc);
}

// ---------------------------------------------------------------------------
// k3: out = G + 0.1*grav*I, grav dot done ONCE per block (warp 0 -> smem) to
// keep L2 side-traffic negligible. G loads issued before the barrier so they
// stay in flight. Tail: last block resets phisum + counter for next replay.
__global__ __launch_bounds__(256) void k3_copy(
    const float* __restrict__ G, float* __restrict__ out)
{
    __shared__ float gs_sh;
    const int tk = blockIdx.x;                   // token id in [0, B*T)
    const int bi = tk >> 12;                     // batch (Tn = 4096)
    const int lane = threadIdx.x & 31;
    const long base4 = (long)tk * 1024;          // float4 units
    const float4* __restrict__ Gp = (const float4*)G;
    float4* __restrict__ Op = (float4*)out;

    // Issue the DRAM loads first; they remain in flight across the barrier.
    float4 v[4];
    #pragma unroll
    for (int it = 0; it < 4; ++it)
        v[it] = __ldcs(&Gp[base4 + threadIdx.x + it * 256]);

    // Warp 0 computes grav = dot(phi[tk,:], phisum[bi,:]) once.
    if (threadIdx.x < 32) {
        const float* __restrict__ phi = &g_phi[(long)tk * Rn];
        const float* __restrict__ ps  = &g_phisum[bi * Rn];
        float s = phi[lane] * ps[lane] + phi[lane + 32] * ps[lane + 32];
        #pragma unroll
        for (int o = 16; o > 0; o >>= 1) s += __shfl_xor_sync(0xFFFFFFFFu, s, o);
        if (lane == 0) gs_sh = STRENGTH * s;
    }
    __syncthreads();
    const float gs = gs_sh;

    #pragma unroll
    for (int it = 0; it < 4; ++it) {
        const int k = threadIdx.x + it * 256;    // float4 index in tile
        const int m = (4 * k) % 65;              // diag iff (4k + comp) % 65 == 0
        if      (m == 0)  v[it].x += gs;
        else if (m == 64) v[it].y += gs;
        else if (m == 63) v[it].z += gs;
        else if (m == 62) v[it].w += gs;
        __stcs(&Op[base4 + k], v[it]);
    }

    // Replay-state reset: last block to finish zeroes phisum and the counter.
    if (threadIdx.x == 0) {
        __threadfence();
        const unsigned int done = atomicAdd(&g_ctr, 1u);
        if (done == (unsigned int)(NTOK - 1)) {
            for (int i = 0; i < Bn * Rn; ++i) g_phisum[i] = 0.0f;
            g_ctr = 0u;
        }
    }
}

// ---------------------------------------------------------------------------
extern "C" void kernel_launch(void* const* d_in, const int* in_sizes, int n_in,
                              void* d_out, int out_size) {
    const float* G      = (const float*)d_in[0];
    const float* coords = (const float*)d_in[1];
    const float* w1     = (const float*)d_in[2];
    const float* b1     = (const float*)d_in[3];
    const float* w2     = (const float*)d_in[4];
    const float* b2     = (const float*)d_in[5];
    const float* W      = (const float*)d_in[6];
    const float* b      = (const float*)d_in[7];
    float* out = (float*)d_out;

    k1_phi_mass<<<K1_BLOCKS, 256>>>(coords, w1, b1, w2, b2, W, b);
    k3_copy<<<NTOK, 256>>>(G, out);
}